// round 10
// baseline (speedup 1.0000x reference)
#include <cuda_runtime.h>
#include <math.h>

#define N_POINTS 16384
#define N_PAIRS  65536

#define T_SUPER  16
#define N_SUPER  136                         // upper-triangle 1024x1024 supertiles
#define SUBS_PER_SUPER 8                     // 2 i-halves (512) x 4 j-quarters (256)
#define HEAVY_BLOCKS (N_SUPER * SUBS_PER_SUPER)  // 1088
#define PAIR_BLOCKS  64
#define NBLOCKS  (HEAVY_BLOCKS + PAIR_BLOCKS)    // 1152
#define JTILE 256

typedef unsigned int u32;

// ---- device scratch (no allocation allowed) ----------------------------------
__device__ float g_part_p[HEAVY_BLOCKS];
__device__ float g_kld_p[PAIR_BLOCKS];
__device__ float g_pair_p[PAIR_BLOCKS];
__device__ float g_pij_p[PAIR_BLOCKS];
__device__ unsigned int g_ticket = 0;

__device__ __forceinline__ float rcp_fast(float x) {
    float r; asm("rcp.approx.f32 %0, %1;" : "=f"(r) : "f"(x)); return r;
}

// ---- reductions ----------------------------------------------------------------
__device__ __forceinline__ float warp_reduce(float v) {
    #pragma unroll
    for (int o = 16; o > 0; o >>= 1) v += __shfl_xor_sync(0xffffffffu, v, o);
    return v;
}
__device__ __forceinline__ float block_reduce(float v, float* smem) {
    v = warp_reduce(v);
    int lane = threadIdx.x & 31, wid = threadIdx.x >> 5;
    if (lane == 0) smem[wid] = v;
    __syncthreads();
    v = (threadIdx.x < 8) ? smem[threadIdx.x] : 0.0f;
    if (wid == 0) {
        #pragma unroll
        for (int o = 4; o > 0; o >>= 1) v += __shfl_xor_sync(0xffffffffu, v, o);
    }
    return v;  // valid in thread 0
}

// ---- reparam helper: x = eps*exp(0.5*lv) + mu ----------------------------------
__device__ __forceinline__ float2 reparam_pt(const float* __restrict__ mu,
                                             const float* __restrict__ lv,
                                             const float* __restrict__ eps,
                                             int idx) {
    float2 m = ((const float2*)mu)[idx];
    float2 l = ((const float2*)lv)[idx];
    float2 e = ((const float2*)eps)[idx];
    float2 x;
    x.x = fmaf(e.x, __expf(0.5f * l.x), m.x);
    x.y = fmaf(e.y, __expf(0.5f * l.y), m.y);
    return x;
}

// ---- single fused kernel --------------------------------------------------------
__global__ __launch_bounds__(256, 5)
void k_main(const float* __restrict__ pij,
            const int*   __restrict__ ii,
            const int*   __restrict__ jj,
            const float* __restrict__ mu,
            const float* __restrict__ lv,
            const float* __restrict__ epsf,
            const float* __restrict__ epsi,
            const float* __restrict__ epsj,
            float* __restrict__ out) {
    __shared__ __align__(16) float4 s_j[JTILE];   // per j: (cx=-2xjx, cy=-2xjy, b=1+|xj|^2, 0)
    __shared__ float  sred[8];
    __shared__ float  sred1[8];
    __shared__ double sdd[256];
    __shared__ unsigned int s_last;

    const int bid = blockIdx.x;
    const int tid = threadIdx.x;

    if (bid < HEAVY_BLOCKS) {
        // -------- heavy path: supertile s, sub-block (i-half, j-quarter) --------
        int s = bid >> 3;
        int sub = bid & 7;
        int a = 0, rem = s;
        while (rem >= T_SUPER - a) { rem -= T_SUPER - a; a++; }
        int b = a + rem;
        int i0 = a * 1024 + (sub >> 2) * 512;
        int j0 = b * 1024 + (sub & 3)  * JTILE;
        float wt = (a == b) ? 1.0f : 2.0f;

        // build j-tile in shared (reparam on the fly)
        {
            float2 xj = reparam_pt(mu, lv, epsf, j0 + tid);
            s_j[tid] = make_float4(-2.0f * xj.x, -2.0f * xj.y,
                                   fmaf(xj.x, xj.x, fmaf(xj.y, xj.y, 1.0f)), 0.0f);
        }

        // two i-chains per thread (512 i per CTA)
        float2 xa = reparam_pt(mu, lv, epsf, i0 + tid);
        float2 xb = reparam_pt(mu, lv, epsf, i0 + 256 + tid);
        float ha = fmaf(xa.x, xa.x, xa.y * xa.y);   // |xi|^2
        float hb = fmaf(xb.x, xb.x, xb.y * xb.y);

        float accNa = 0.0f, accNb = 0.0f;   // newton-path accumulators
        float accMa = 0.0f, accMb = 0.0f;   // mufu-path accumulators

        __syncthreads();

        // 8 j's per step: 3 newton (fma+alu pipes) + 5 mufu (MUFU pipe)
        #pragma unroll 2
        for (int it = 0; it < JTILE / 8; it++) {
            const float4* jp = s_j + it * 8;
            #pragma unroll
            for (int k = 0; k < 3; k++) {
                float4 v = jp[k];
                float d0 = fmaf(v.x, xa.x, fmaf(v.y, xa.y, v.z + ha));
                float y0 = __uint_as_float(0x7EF127EAu - __float_as_uint(d0));
                accNa = fmaf(y0, fmaf(-d0, y0, 2.0f), accNa);
                float d1 = fmaf(v.x, xb.x, fmaf(v.y, xb.y, v.z + hb));
                float y1 = __uint_as_float(0x7EF127EAu - __float_as_uint(d1));
                accNb = fmaf(y1, fmaf(-d1, y1, 2.0f), accNb);
            }
            #pragma unroll
            for (int k = 3; k < 8; k++) {
                float4 v = jp[k];
                float d0 = fmaf(v.x, xa.x, fmaf(v.y, xa.y, v.z + ha));
                accMa += rcp_fast(d0);
                float d1 = fmaf(v.x, xb.x, fmaf(v.y, xb.y, v.z + hb));
                accMb += rcp_fast(d1);
            }
        }

        float sres = block_reduce((accNa + accNb) + (accMa + accMb), sred);
        if (tid == 0) g_part_p[bid] = sres * wt;
    } else {
        // -------- pairs path + KLD slice -----------------------------------------
        int pb = bid - HEAVY_BLOCKS;
        float term = 0.0f, psum = 0.0f;
        int base = pb * 1024;
        #pragma unroll
        for (int r = 0; r < 4; r++) {
            int p = base + r * 256 + tid;
            int ai = ii[p], bi = jj[p];
            float2 ma = ((const float2*)mu)[ai];
            float2 la = ((const float2*)lv)[ai];
            float2 ea = ((const float2*)epsi)[p];
            float2 mb = ((const float2*)mu)[bi];
            float2 lb = ((const float2*)lv)[bi];
            float2 eb = ((const float2*)epsj)[p];
            float xax = fmaf(ea.x, __expf(0.5f * la.x), ma.x);
            float xay = fmaf(ea.y, __expf(0.5f * la.y), ma.y);
            float xbx = fmaf(eb.x, __expf(0.5f * lb.x), mb.x);
            float xby = fmaf(eb.y, __expf(0.5f * lb.y), mb.y);
            float da = xax - xbx, db = xay - xby;
            float d2 = fmaf(da, da, db * db);
            float pv = pij[p];
            // pij*(log pij - log qij) = pij*(log pij + log(1+d2)) + pij*log(part)
            term += pv * (logf(pv) + log1pf(d2));
            psum += pv;
        }
        // KLD slice: 256 points per pair-block (64 * 256 = 16384)
        float kld;
        {
            int idx = pb * 256 + tid;
            float2 m = ((const float2*)mu)[idx];
            float2 l = ((const float2*)lv)[idx];
            kld = (1.0f + l.x - m.x * m.x - __expf(l.x))
                + (1.0f + l.y - m.y * m.y - __expf(l.y));
        }
        float s0 = block_reduce(term, sred);
        __syncthreads();
        float s1 = block_reduce(psum, sred1);
        __syncthreads();
        float s2 = block_reduce(kld, sred);
        if (tid == 0) {
            g_pair_p[pb] = s0;
            g_pij_p[pb]  = s1;
            g_kld_p[pb]  = s2;
        }
    }

    // -------- fused final: last CTA reduces everything ----------------------------
    __threadfence();
    if (tid == 0) s_last = atomicAdd(&g_ticket, 1u);
    __syncthreads();
    if (s_last == NBLOCKS - 1) {
        __threadfence();
        double part = 0.0, kld = 0.0, pair = 0.0, pijs = 0.0;
        for (int t = tid; t < HEAVY_BLOCKS; t += 256) part += (double)g_part_p[t];
        if (tid < PAIR_BLOCKS) {
            kld  = (double)g_kld_p[tid];
            pair = (double)g_pair_p[tid];
            pijs = (double)g_pij_p[tid];
        }
        double vals[4] = {part, kld, pair, pijs};
        double res[4];
        #pragma unroll
        for (int k = 0; k < 4; k++) {
            sdd[tid] = vals[k];
            __syncthreads();
            for (int o = 128; o > 0; o >>= 1) {
                if (tid < o) sdd[tid] += sdd[tid + o];
                __syncthreads();
            }
            res[k] = sdd[0];
            __syncthreads();
        }
        if (tid == 0) {
            double partv = res[0] - (double)N_POINTS;   // remove diagonal
            double loss = res[2] + res[3] * log(partv) + 1e-7 * (-0.5 * res[1]);
            out[0] = (float)loss;
            g_ticket = 0;   // reset for next graph replay
        }
    }
}

// -----------------------------------------------------------------------------
extern "C" void kernel_launch(void* const* d_in, const int* in_sizes, int n_in,
                              void* d_out, int out_size) {
    const float* pij      = (const float*)d_in[0];
    const int*   i_idx    = (const int*)  d_in[1];
    const int*   j_idx    = (const int*)  d_in[2];
    const float* mu_w     = (const float*)d_in[3];
    const float* lv_w     = (const float*)d_in[4];
    const float* eps_full = (const float*)d_in[5];
    const float* eps_i    = (const float*)d_in[6];
    const float* eps_j    = (const float*)d_in[7];
    float* out = (float*)d_out;

    k_main<<<NBLOCKS, 256>>>(pij, i_idx, j_idx, mu_w, lv_w,
                             eps_full, eps_i, eps_j, out);
}

// round 11
// speedup vs baseline: 1.0115x; 1.0115x over previous
#include <cuda_runtime.h>
#include <math.h>

#define N_POINTS 16384
#define N_PAIRS  65536

#define T_GRID   32                      // 32x32 tiles of 512 points
#define HEAVY_BLOCKS 528                 // T*(T+1)/2 upper-triangle tiles (512x512)
#define PAIR_BLOCKS  64
#define NBLOCKS  (HEAVY_BLOCKS + PAIR_BLOCKS)    // 592 = 4 * 148 exactly
#define JTILE 512
#define JPAIRS (JTILE / 2)               // 256 packed j-pairs
#define JGROUPS (JPAIRS / 4)             // 64 groups of 4 pairs (3 mufu + 1 newton)

typedef unsigned long long u64;
typedef unsigned int u32;

// ---- device scratch (no allocation allowed) ----------------------------------
__device__ float g_part_p[HEAVY_BLOCKS];
__device__ float g_kld_p[PAIR_BLOCKS];
__device__ float g_pair_p[PAIR_BLOCKS];
__device__ float g_pij_p[PAIR_BLOCKS];
__device__ unsigned int g_ticket = 0;

// ---- packed f32x2 helpers -----------------------------------------------------
__device__ __forceinline__ u64 pack2(float lo, float hi) {
    u64 r; asm("mov.b64 %0, {%1, %2};" : "=l"(r) : "f"(lo), "f"(hi)); return r;
}
__device__ __forceinline__ void unpack2f(float& lo, float& hi, u64 v) {
    asm("mov.b64 {%0, %1}, %2;" : "=f"(lo), "=f"(hi) : "l"(v));
}
__device__ __forceinline__ u64 fma2(u64 a, u64 b, u64 c) {
    u64 d; asm("fma.rn.f32x2 %0, %1, %2, %3;" : "=l"(d) : "l"(a), "l"(b), "l"(c)); return d;
}
__device__ __forceinline__ u64 add2(u64 a, u64 b) {
    u64 d; asm("add.rn.f32x2 %0, %1, %2;" : "=l"(d) : "l"(a), "l"(b)); return d;
}
__device__ __forceinline__ float rcp_fast(float x) {
    float r; asm("rcp.approx.f32 %0, %1;" : "=f"(r) : "f"(x)); return r;
}

// ---- reductions ----------------------------------------------------------------
__device__ __forceinline__ float warp_reduce(float v) {
    #pragma unroll
    for (int o = 16; o > 0; o >>= 1) v += __shfl_xor_sync(0xffffffffu, v, o);
    return v;
}
__device__ __forceinline__ float block_reduce(float v, float* smem) {
    v = warp_reduce(v);
    int lane = threadIdx.x & 31, wid = threadIdx.x >> 5;
    if (lane == 0) smem[wid] = v;
    __syncthreads();
    v = (threadIdx.x < 8) ? smem[threadIdx.x] : 0.0f;
    if (wid == 0) {
        #pragma unroll
        for (int o = 4; o > 0; o >>= 1) v += __shfl_xor_sync(0xffffffffu, v, o);
    }
    return v;  // valid in thread 0
}

// ---- reparam helper: x = eps*exp(0.5*lv) + mu ----------------------------------
__device__ __forceinline__ float2 reparam_pt(const float* __restrict__ mu,
                                             const float* __restrict__ lv,
                                             const float* __restrict__ eps,
                                             int idx) {
    float2 m = ((const float2*)mu)[idx];
    float2 l = ((const float2*)lv)[idx];
    float2 e = ((const float2*)eps)[idx];
    float2 x;
    x.x = fmaf(e.x, __expf(0.5f * l.x), m.x);
    x.y = fmaf(e.y, __expf(0.5f * l.y), m.y);
    return x;
}

// packed d = (1 + |xj|^2 + |xi|^2) - 2 xi.xj = 1 + dist^2 for a j-pair
__device__ __forceinline__ u64 dist2p(ulonglong2 cc, u64 b2, u64 xix2, u64 xiy2, u64 h2) {
    return fma2(cc.x, xix2, fma2(cc.y, xiy2, add2(b2, h2)));
}

// ---- single fused kernel --------------------------------------------------------
__global__ __launch_bounds__(256, 5)
void k_main(const float* __restrict__ pij,
            const int*   __restrict__ ii,
            const int*   __restrict__ jj,
            const float* __restrict__ mu,
            const float* __restrict__ lv,
            const float* __restrict__ epsf,
            const float* __restrict__ epsi,
            const float* __restrict__ epsj,
            float* __restrict__ out) {
    __shared__ __align__(16) ulonglong2 s_cxy[JPAIRS];  // per j-pair: (cx01, cy01), c=-2x
    __shared__ __align__(16) u64        s_b[JPAIRS];    // per j-pair: (1+|xj|^2) pair
    __shared__ float  sred[8];
    __shared__ float  sred1[8];
    __shared__ double sdd[256];
    __shared__ unsigned int s_last;

    const int bid = blockIdx.x;
    const int tid = threadIdx.x;

    if (bid < HEAVY_BLOCKS) {
        // -------- heavy path: upper-tri tile (a,b), 512x512 ----------------------
        int a = 0, rem = bid;
        while (rem >= T_GRID - a) { rem -= T_GRID - a; a++; }
        int b = a + rem;
        int i0 = a * 512;
        int j0 = b * 512;
        float wt = (a == b) ? 1.0f : 2.0f;

        // build j-tile in shared (reparam on the fly): 512 j's -> 256 pairs
        #pragma unroll
        for (int r = 0; r < 2; r++) {
            int jg = j0 + r * 256 + tid;
            float2 xj = reparam_pt(mu, lv, epsf, jg);
            float cx = -2.0f * xj.x, cy = -2.0f * xj.y;
            float bb = fmaf(xj.x, xj.x, fmaf(xj.y, xj.y, 1.0f));
            float cxn = __shfl_down_sync(0xffffffffu, cx, 1);
            float cyn = __shfl_down_sync(0xffffffffu, cy, 1);
            float bbn = __shfl_down_sync(0xffffffffu, bb, 1);
            if ((tid & 1) == 0) {
                int p = (r * 256 + tid) >> 1;
                ulonglong2 w;
                w.x = pack2(cx, cxn);
                w.y = pack2(cy, cyn);
                s_cxy[p] = w;
                s_b[p] = pack2(bb, bbn);
            }
        }

        // two i-chains per thread (512 i per CTA)
        float2 xa = reparam_pt(mu, lv, epsf, i0 + tid);
        float2 xb = reparam_pt(mu, lv, epsf, i0 + 256 + tid);
        u64 xax2 = pack2(xa.x, xa.x), xay2 = pack2(xa.y, xa.y);
        u64 xbx2 = pack2(xb.x, xb.x), xby2 = pack2(xb.y, xb.y);
        float haf = fmaf(xa.x, xa.x, xa.y * xa.y);   // |xi|^2
        float hbf = fmaf(xb.x, xb.x, xb.y * xb.y);
        u64 ha2 = pack2(haf, haf);
        u64 hb2 = pack2(hbf, hbf);
        const u64 TWO2   = pack2(2.0f, 2.0f);
        const u64 MAGIC2 = 0xFEF127EAFEF127EAull;    // negated magic seed (both halves)

        u64 accNa = 0ull, accNb = 0ull;              // packed newton accs (negated sums)
        float accMa0 = 0.0f, accMa1 = 0.0f;          // scalar mufu accs, chain a
        float accMb0 = 0.0f, accMb1 = 0.0f;          // scalar mufu accs, chain b

        __syncthreads();

        // groups of 4 j-pairs: pairs 0..2 -> MUFU.RCP, pair 3 -> packed newton
        #pragma unroll 2
        for (int g = 0; g < JGROUPS; g++) {
            int p4 = g * 4;
            // ---- mufu pairs (fma pipe: 3 fma2 each; rcp on MUFU; acc on alu) ----
            #pragma unroll
            for (int k = 0; k < 3; k++) {
                ulonglong2 cc = s_cxy[p4 + k];
                u64 b2 = s_b[p4 + k];
                u64 da = dist2p(cc, b2, xax2, xay2, ha2);
                float dal, dah; unpack2f(dal, dah, da);
                accMa0 += rcp_fast(dal);
                accMa1 += rcp_fast(dah);
                u64 db = dist2p(cc, b2, xbx2, xby2, hb2);
                float dbl_, dbh; unpack2f(dbl_, dbh, db);
                accMb0 += rcp_fast(dbl_);
                accMb1 += rcp_fast(dbh);
            }
            // ---- newton pair (uses leftover fma capacity) -----------------------
            {
                ulonglong2 cc = s_cxy[p4 + 3];
                u64 b2 = s_b[p4 + 3];
                u64 da = dist2p(cc, b2, xax2, xay2, ha2);
                u64 ya = MAGIC2 - da;               // ~ -(1/d), per-half, no borrow
                u64 ta = fma2(da, ya, TWO2);        // 2 - d*y
                accNa = fma2(ya, ta, accNa);        // acc -= y*(2-d*y)
                u64 db = dist2p(cc, b2, xbx2, xby2, hb2);
                u64 yb = MAGIC2 - db;
                u64 tb = fma2(db, yb, TWO2);
                accNb = fma2(yb, tb, accNb);
            }
        }

        float nal, nah, nbl, nbh;
        unpack2f(nal, nah, accNa);
        unpack2f(nbl, nbh, accNb);
        float total = (accMa0 + accMa1) + (accMb0 + accMb1)
                    - ((nal + nah) + (nbl + nbh));   // newton accs are negated
        float sres = block_reduce(total, sred);
        if (tid == 0) g_part_p[bid] = sres * wt;
    } else {
        // -------- pairs path + KLD slice -----------------------------------------
        int pb = bid - HEAVY_BLOCKS;
        float term = 0.0f, psum = 0.0f;
        int base = pb * 1024;
        #pragma unroll
        for (int r = 0; r < 4; r++) {
            int p = base + r * 256 + tid;
            int ai = ii[p], bi = jj[p];
            float2 ma = ((const float2*)mu)[ai];
            float2 la = ((const float2*)lv)[ai];
            float2 ea = ((const float2*)epsi)[p];
            float2 mb = ((const float2*)mu)[bi];
            float2 lb = ((const float2*)lv)[bi];
            float2 eb = ((const float2*)epsj)[p];
            float xax = fmaf(ea.x, __expf(0.5f * la.x), ma.x);
            float xay = fmaf(ea.y, __expf(0.5f * la.y), ma.y);
            float xbx = fmaf(eb.x, __expf(0.5f * lb.x), mb.x);
            float xby = fmaf(eb.y, __expf(0.5f * lb.y), mb.y);
            float da = xax - xbx, db = xay - xby;
            float d2 = fmaf(da, da, db * db);
            float pv = pij[p];
            // pij*(log pij - log qij) = pij*(log pij + log(1+d2)) + pij*log(part)
            term += pv * (logf(pv) + log1pf(d2));
            psum += pv;
        }
        // KLD slice: 256 points per pair-block (64 * 256 = 16384)
        float kld;
        {
            int idx = pb * 256 + tid;
            float2 m = ((const float2*)mu)[idx];
            float2 l = ((const float2*)lv)[idx];
            kld = (1.0f + l.x - m.x * m.x - __expf(l.x))
                + (1.0f + l.y - m.y * m.y - __expf(l.y));
        }
        float s0 = block_reduce(term, sred);
        __syncthreads();
        float s1 = block_reduce(psum, sred1);
        __syncthreads();
        float s2 = block_reduce(kld, sred);
        if (tid == 0) {
            g_pair_p[pb] = s0;
            g_pij_p[pb]  = s1;
            g_kld_p[pb]  = s2;
        }
    }

    // -------- fused final: last CTA reduces everything ----------------------------
    __threadfence();
    if (tid == 0) s_last = atomicAdd(&g_ticket, 1u);
    __syncthreads();
    if (s_last == NBLOCKS - 1) {
        __threadfence();
        double part = 0.0, kld = 0.0, pair = 0.0, pijs = 0.0;
        for (int t = tid; t < HEAVY_BLOCKS; t += 256) part += (double)g_part_p[t];
        if (tid < PAIR_BLOCKS) {
            kld  = (double)g_kld_p[tid];
            pair = (double)g_pair_p[tid];
            pijs = (double)g_pij_p[tid];
        }
        double vals[4] = {part, kld, pair, pijs};
        double res[4];
        #pragma unroll
        for (int k = 0; k < 4; k++) {
            sdd[tid] = vals[k];
            __syncthreads();
            for (int o = 128; o > 0; o >>= 1) {
                if (tid < o) sdd[tid] += sdd[tid + o];
                __syncthreads();
            }
            res[k] = sdd[0];
            __syncthreads();
        }
        if (tid == 0) {
            double partv = res[0] - (double)N_POINTS;   // remove diagonal
            double loss = res[2] + res[3] * log(partv) + 1e-7 * (-0.5 * res[1]);
            out[0] = (float)loss;
            g_ticket = 0;   // reset for next graph replay
        }
    }
}

// -----------------------------------------------------------------------------
extern "C" void kernel_launch(void* const* d_in, const int* in_sizes, int n_in,
                              void* d_out, int out_size) {
    const float* pij      = (const float*)d_in[0];
    const int*   i_idx    = (const int*)  d_in[1];
    const int*   j_idx    = (const int*)  d_in[2];
    const float* mu_w     = (const float*)d_in[3];
    const float* lv_w     = (const float*)d_in[4];
    const float* eps_full = (const float*)d_in[5];
    const float* eps_i    = (const float*)d_in[6];
    const float* eps_j    = (const float*)d_in[7];
    float* out = (float*)d_out;

    k_main<<<NBLOCKS, 256>>>(pij, i_idx, j_idx, mu_w, lv_w,
                             eps_full, eps_i, eps_j, out);
}

// round 12
// speedup vs baseline: 1.3585x; 1.3431x over previous
#include <cuda_runtime.h>
#include <math.h>

#define N_POINTS 16384
#define N_PAIRS  65536

#define T_SUPER  16
#define N_SUPER  136                         // upper-tri 1024x1024 supertiles
#define SUBS_PER_SUPER 4                     // 4 j-quarters; all 1024 i per CTA
#define HEAVY_BLOCKS (N_SUPER * SUBS_PER_SUPER)  // 544
#define PAIR_BLOCKS  64
#define NBLOCKS  (HEAVY_BLOCKS + PAIR_BLOCKS)    // 608
#define JTILE 256
#define JPAIRS (JTILE / 2)                   // 128 packed j-pairs

typedef unsigned long long u64;
typedef unsigned int u32;

// ---- device scratch (no allocation allowed) ----------------------------------
__device__ float g_part_p[HEAVY_BLOCKS];
__device__ float g_kld_p[PAIR_BLOCKS];
__device__ float g_pair_p[PAIR_BLOCKS];
__device__ float g_pij_p[PAIR_BLOCKS];
__device__ unsigned int g_ticket = 0;

// ---- packed f32x2 helpers -----------------------------------------------------
__device__ __forceinline__ u64 pack2(float lo, float hi) {
    u64 r; asm("mov.b64 %0, {%1, %2};" : "=l"(r) : "f"(lo), "f"(hi)); return r;
}
__device__ __forceinline__ void unpack2f(float& lo, float& hi, u64 v) {
    asm("mov.b64 {%0, %1}, %2;" : "=f"(lo), "=f"(hi) : "l"(v));
}
__device__ __forceinline__ u64 fma2(u64 a, u64 b, u64 c) {
    u64 d; asm("fma.rn.f32x2 %0, %1, %2, %3;" : "=l"(d) : "l"(a), "l"(b), "l"(c)); return d;
}
__device__ __forceinline__ u64 add2(u64 a, u64 b) {
    u64 d; asm("add.rn.f32x2 %0, %1, %2;" : "=l"(d) : "l"(a), "l"(b)); return d;
}

// ---- reductions ----------------------------------------------------------------
__device__ __forceinline__ float warp_reduce(float v) {
    #pragma unroll
    for (int o = 16; o > 0; o >>= 1) v += __shfl_xor_sync(0xffffffffu, v, o);
    return v;
}
__device__ __forceinline__ float block_reduce(float v, float* smem) {
    v = warp_reduce(v);
    int lane = threadIdx.x & 31, wid = threadIdx.x >> 5;
    if (lane == 0) smem[wid] = v;
    __syncthreads();
    v = (threadIdx.x < 8) ? smem[threadIdx.x] : 0.0f;
    if (wid == 0) {
        #pragma unroll
        for (int o = 4; o > 0; o >>= 1) v += __shfl_xor_sync(0xffffffffu, v, o);
    }
    return v;  // valid in thread 0
}

// ---- reparam helper: x = eps*exp(0.5*lv) + mu ----------------------------------
__device__ __forceinline__ float2 reparam_pt(const float* __restrict__ mu,
                                             const float* __restrict__ lv,
                                             const float* __restrict__ eps,
                                             int idx) {
    float2 m = ((const float2*)mu)[idx];
    float2 l = ((const float2*)lv)[idx];
    float2 e = ((const float2*)eps)[idx];
    float2 x;
    x.x = fmaf(e.x, __expf(0.5f * l.x), m.x);
    x.y = fmaf(e.y, __expf(0.5f * l.y), m.y);
    return x;
}

// ---- single fused kernel --------------------------------------------------------
__global__ __launch_bounds__(256, 4)
void k_main(const float* __restrict__ pij,
            const int*   __restrict__ ii,
            const int*   __restrict__ jj,
            const float* __restrict__ mu,
            const float* __restrict__ lv,
            const float* __restrict__ epsf,
            const float* __restrict__ epsi,
            const float* __restrict__ epsj,
            float* __restrict__ out) {
    __shared__ __align__(16) ulonglong2 s_cxy[JPAIRS];  // per j-pair: (cx01, cy01), c=-2x
    __shared__ __align__(16) u64        s_b[JPAIRS];    // per j-pair: (1+|xj|^2) pair
    __shared__ float  sred[8];
    __shared__ float  sred1[8];
    __shared__ double sdd[256];
    __shared__ unsigned int s_last;

    const int bid = blockIdx.x;
    const int tid = threadIdx.x;

    if (bid < HEAVY_BLOCKS) {
        // -------- heavy path: supertile s (1024 i), j-quarter sub (256 j) --------
        int s = bid >> 2;
        int sub = bid & 3;
        int a = 0, rem = s;
        while (rem >= T_SUPER - a) { rem -= T_SUPER - a; a++; }
        int b = a + rem;
        int i0 = a * 1024;
        int j0 = b * 1024 + sub * JTILE;
        float wt = (a == b) ? 1.0f : 2.0f;

        // build j-tile in shared (reparam on the fly): 256 j's -> 128 pairs
        {
            float2 xj = reparam_pt(mu, lv, epsf, j0 + tid);
            float cx = -2.0f * xj.x, cy = -2.0f * xj.y;
            float bb = fmaf(xj.x, xj.x, fmaf(xj.y, xj.y, 1.0f));
            float cxn = __shfl_down_sync(0xffffffffu, cx, 1);
            float cyn = __shfl_down_sync(0xffffffffu, cy, 1);
            float bbn = __shfl_down_sync(0xffffffffu, bb, 1);
            if ((tid & 1) == 0) {
                int p = tid >> 1;
                ulonglong2 w;
                w.x = pack2(cx, cxn);
                w.y = pack2(cy, cyn);
                s_cxy[p] = w;
                s_b[p] = pack2(bb, bbn);
            }
        }

        // FOUR i-chains per thread (1024 i per CTA)
        float2 x0 = reparam_pt(mu, lv, epsf, i0 + tid);
        float2 x1 = reparam_pt(mu, lv, epsf, i0 + 256 + tid);
        float2 x2 = reparam_pt(mu, lv, epsf, i0 + 512 + tid);
        float2 x3 = reparam_pt(mu, lv, epsf, i0 + 768 + tid);
        u64 xx0 = pack2(x0.x, x0.x), xy0 = pack2(x0.y, x0.y);
        u64 xx1 = pack2(x1.x, x1.x), xy1 = pack2(x1.y, x1.y);
        u64 xx2 = pack2(x2.x, x2.x), xy2 = pack2(x2.y, x2.y);
        u64 xx3 = pack2(x3.x, x3.x), xy3 = pack2(x3.y, x3.y);
        float h0f = fmaf(x0.x, x0.x, x0.y * x0.y);
        float h1f = fmaf(x1.x, x1.x, x1.y * x1.y);
        float h2f = fmaf(x2.x, x2.x, x2.y * x2.y);
        float h3f = fmaf(x3.x, x3.x, x3.y * x3.y);
        u64 h0 = pack2(h0f, h0f), h1 = pack2(h1f, h1f);
        u64 h2 = pack2(h2f, h2f), h3 = pack2(h3f, h3f);
        const u64 TWO2   = pack2(2.0f, 2.0f);
        const u64 MAGIC2 = 0xFEF127EAFEF127EAull;
        u64 acc0 = 0ull, acc1 = 0ull, acc2 = 0ull, acc3 = 0ull;

        __syncthreads();

        #pragma unroll 4
        for (int p = 0; p < JPAIRS; p++) {
            ulonglong2 cc = s_cxy[p];   // LDS.128 (broadcast)
            u64 b2 = s_b[p];            // LDS.64  (broadcast)
            // d = (1 + |xj|^2 + |xi|^2) - 2 xi.xj = 1 + dist^2 >= 1; acc -= 1/d
            u64 d0 = fma2(cc.x, xx0, fma2(cc.y, xy0, add2(b2, h0)));
            u64 y0 = MAGIC2 - d0;
            acc0 = fma2(y0, fma2(d0, y0, TWO2), acc0);

            u64 d1 = fma2(cc.x, xx1, fma2(cc.y, xy1, add2(b2, h1)));
            u64 y1 = MAGIC2 - d1;
            acc1 = fma2(y1, fma2(d1, y1, TWO2), acc1);

            u64 d2 = fma2(cc.x, xx2, fma2(cc.y, xy2, add2(b2, h2)));
            u64 y2 = MAGIC2 - d2;
            acc2 = fma2(y2, fma2(d2, y2, TWO2), acc2);

            u64 d3 = fma2(cc.x, xx3, fma2(cc.y, xy3, add2(b2, h3)));
            u64 y3 = MAGIC2 - d3;
            acc3 = fma2(y3, fma2(d3, y3, TWO2), acc3);
        }

        float l0, hh0, l1, hh1, l2, hh2, l3, hh3;
        unpack2f(l0, hh0, acc0);
        unpack2f(l1, hh1, acc1);
        unpack2f(l2, hh2, acc2);
        unpack2f(l3, hh3, acc3);
        // accs hold negated sums
        float total = -(((l0 + hh0) + (l1 + hh1)) + ((l2 + hh2) + (l3 + hh3)));
        float sres = block_reduce(total, sred);
        if (tid == 0) g_part_p[bid] = sres * wt;
    } else {
        // -------- pairs path + KLD slice -----------------------------------------
        int pb = bid - HEAVY_BLOCKS;
        float term = 0.0f, psum = 0.0f;
        int base = pb * 1024;
        #pragma unroll
        for (int r = 0; r < 4; r++) {
            int p = base + r * 256 + tid;
            int ai = ii[p], bi = jj[p];
            float2 ma = ((const float2*)mu)[ai];
            float2 la = ((const float2*)lv)[ai];
            float2 ea = ((const float2*)epsi)[p];
            float2 mb = ((const float2*)mu)[bi];
            float2 lb = ((const float2*)lv)[bi];
            float2 eb = ((const float2*)epsj)[p];
            float xax = fmaf(ea.x, __expf(0.5f * la.x), ma.x);
            float xay = fmaf(ea.y, __expf(0.5f * la.y), ma.y);
            float xbx = fmaf(eb.x, __expf(0.5f * lb.x), mb.x);
            float xby = fmaf(eb.y, __expf(0.5f * lb.y), mb.y);
            float da = xax - xbx, db = xay - xby;
            float d2 = fmaf(da, da, db * db);
            float pv = pij[p];
            // pij*(log pij - log qij) = pij*(log pij + log(1+d2)) + pij*log(part)
            term += pv * (logf(pv) + log1pf(d2));
            psum += pv;
        }
        // KLD slice: 256 points per pair-block (64 * 256 = 16384)
        float kld;
        {
            int idx = pb * 256 + tid;
            float2 m = ((const float2*)mu)[idx];
            float2 l = ((const float2*)lv)[idx];
            kld = (1.0f + l.x - m.x * m.x - __expf(l.x))
                + (1.0f + l.y - m.y * m.y - __expf(l.y));
        }
        float s0 = block_reduce(term, sred);
        __syncthreads();
        float s1 = block_reduce(psum, sred1);
        __syncthreads();
        float s2 = block_reduce(kld, sred);
        if (tid == 0) {
            g_pair_p[pb] = s0;
            g_pij_p[pb]  = s1;
            g_kld_p[pb]  = s2;
        }
    }

    // -------- fused final: last CTA reduces everything ----------------------------
    __threadfence();
    if (tid == 0) s_last = atomicAdd(&g_ticket, 1u);
    __syncthreads();
    if (s_last == NBLOCKS - 1) {
        __threadfence();
        double part = 0.0, kld = 0.0, pair = 0.0, pijs = 0.0;
        for (int t = tid; t < HEAVY_BLOCKS; t += 256) part += (double)g_part_p[t];
        if (tid < PAIR_BLOCKS) {
            kld  = (double)g_kld_p[tid];
            pair = (double)g_pair_p[tid];
            pijs = (double)g_pij_p[tid];
        }
        double vals[4] = {part, kld, pair, pijs};
        double res[4];
        #pragma unroll
        for (int k = 0; k < 4; k++) {
            sdd[tid] = vals[k];
            __syncthreads();
            for (int o = 128; o > 0; o >>= 1) {
                if (tid < o) sdd[tid] += sdd[tid + o];
                __syncthreads();
            }
            res[k] = sdd[0];
            __syncthreads();
        }
        if (tid == 0) {
            double partv = res[0] - (double)N_POINTS;   // remove diagonal
            double loss = res[2] + res[3] * log(partv) + 1e-7 * (-0.5 * res[1]);
            out[0] = (float)loss;
            g_ticket = 0;   // reset for next graph replay
        }
    }
}

// -----------------------------------------------------------------------------
extern "C" void kernel_launch(void* const* d_in, const int* in_sizes, int n_in,
                              void* d_out, int out_size) {
    const float* pij      = (const float*)d_in[0];
    const int*   i_idx    = (const int*)  d_in[1];
    const int*   j_idx    = (const int*)  d_in[2];
    const float* mu_w     = (const float*)d_in[3];
    const float* lv_w     = (const float*)d_in[4];
    const float* eps_full = (const float*)d_in[5];
    const float* eps_i    = (const float*)d_in[6];
    const float* eps_j    = (const float*)d_in[7];
    float* out = (float*)d_out;

    k_main<<<NBLOCKS, 256>>>(pij, i_idx, j_idx, mu_w, lv_w,
                             eps_full, eps_i, eps_j, out);
}